// round 7
// baseline (speedup 1.0000x reference)
#include <cuda_runtime.h>
#include <cuda_bf16.h>

// ---------------------------------------------------------------------------
// DisableGateLSTM: B=64, T=512, E=256, H=512, C=4
// Phase 1: pre[t][row][b] = bias[row] + x_t @ W[:,512:768]^T   (268 MB scratch)
// Phase 2: persistent recurrence, 128 CTAs = 32 row-groups x 4 batch-groups,
//          flag-array barrier per step
// Phase 3: logits = (max_t h) @ fc_w^T + fc_b
// ---------------------------------------------------------------------------

#define T_SEQ 512
#define NB    64
#define NE    256
#define NH    512
#define NG    2048
#define RECUR_CTAS 128

typedef unsigned long long u64;

static __device__ float g_pre[(size_t)T_SEQ * NG * NB];   // [t][row][b]
static __device__ float g_h[2][NH * NB];                  // ping-pong h, [j][b]
static __device__ float g_hmax[NH * NB];                  // [j][b]
static __device__ int   g_flags[RECUR_CTAS];              // step progress flags
static __device__ int   g_count;                          // epilogue barrier
static __device__ int   g_sense;

// ---------------- f32x2 helpers ----------------
static __device__ __forceinline__ u64 fma2(u64 a, u64 b, u64 c) {
    u64 d;
    asm("fma.rn.f32x2 %0, %1, %2, %3;" : "=l"(d) : "l"(a), "l"(b), "l"(c));
    return d;
}
static __device__ __forceinline__ u64 add2(u64 a, u64 b) {
    u64 d;
    asm("add.rn.f32x2 %0, %1, %2;" : "=l"(d) : "l"(a), "l"(b));
    return d;
}
static __device__ __forceinline__ u64 pkdup(float a) {
    u64 r; asm("mov.b64 %0, {%1, %1};" : "=l"(r) : "f"(a)); return r;
}
static __device__ __forceinline__ float2 upk2(u64 a) {
    float2 f;
    asm("mov.b64 {%0, %1}, %2;" : "=f"(f.x), "=f"(f.y) : "l"(a));
    return f;
}
static __device__ __forceinline__ float sigf(float x) {
    return 1.f / (1.f + __expf(-x));
}
static __device__ __forceinline__ float tanh_fast(float x) {
    return 2.f / (1.f + __expf(-2.f * x)) - 1.f;
}
// cp.async.cg: L2-only path => coherent with other SMs' global stores
static __device__ __forceinline__ void cpa16(void* dst, const void* src) {
    unsigned s = (unsigned)__cvta_generic_to_shared(dst);
    asm volatile("cp.async.cg.shared.global [%0], [%1], 16;" :: "r"(s), "l"(src) : "memory");
}

// =====================================================================
// Phase 1: pre-GEMM (unchanged from R5: 832us, fma 52%)
// =====================================================================
__global__ void __launch_bounds__(256, 2) pre_gemm(
    const int* __restrict__ ids, const float* __restrict__ emb,
    const float* __restrict__ Wf, const float* __restrict__ bf,
    const float* __restrict__ Wi, const float* __restrict__ bi,
    const float* __restrict__ Wo, const float* __restrict__ bo,
    const float* __restrict__ Wc, const float* __restrict__ bc)
{
    __shared__ float As[2][16][256];   // [kk][2*j] duplicated pairs
    __shared__ float Bs[2][16][128];   // [kk][m]

    const int t  = threadIdx.x;
    const int gx = blockIdx.x;
    const int m0 = blockIdx.y * 128;
    const int tx = t & 15, ty = t >> 4;

    const float* W    = (gx < 4) ? Wf : (gx < 8) ? Wi : (gx < 12) ? Wo : Wc;
    const float* bias = (gx < 4) ? bf : (gx < 8) ? bi : (gx < 12) ? bo : bc;
    const int jg0 = (gx & 3) * 128;

    const int jA0 = t >> 2;
    const int jA1 = jA0 + 64;
    const int qA  = t & 3;
    const int ml0 = t >> 2;
    const int ml1 = ml0 + 64;
    const int mg0 = m0 + ml0, mg1 = m0 + ml1;
    const int id0 = ids[(mg0 & 63) * T_SEQ + (mg0 >> 6)];
    const int id1 = ids[(mg1 & 63) * T_SEQ + (mg1 >> 6)];

    u64 acc[8][4];
#pragma unroll
    for (int jj = 0; jj < 8; ++jj)
#pragma unroll
        for (int s = 0; s < 4; ++s) acc[jj][s] = 0ull;

    float4 a0, a1, b0v, b1v;
    {
        const int k0 = 0;
        a0  = *(const float4*)&W[(size_t)(jg0 + jA0) * 768 + 512 + k0 + qA * 4];
        a1  = *(const float4*)&W[(size_t)(jg0 + jA1) * 768 + 512 + k0 + qA * 4];
        b0v = *(const float4*)&emb[(size_t)id0 * NE + k0 + qA * 4];
        b1v = *(const float4*)&emb[(size_t)id1 * NE + k0 + qA * 4];
    }
    {
        const int st = 0;
        As[st][qA*4+0][2*jA0] = a0.x; As[st][qA*4+0][2*jA0+1] = a0.x;
        As[st][qA*4+1][2*jA0] = a0.y; As[st][qA*4+1][2*jA0+1] = a0.y;
        As[st][qA*4+2][2*jA0] = a0.z; As[st][qA*4+2][2*jA0+1] = a0.z;
        As[st][qA*4+3][2*jA0] = a0.w; As[st][qA*4+3][2*jA0+1] = a0.w;
        As[st][qA*4+0][2*jA1] = a1.x; As[st][qA*4+0][2*jA1+1] = a1.x;
        As[st][qA*4+1][2*jA1] = a1.y; As[st][qA*4+1][2*jA1+1] = a1.y;
        As[st][qA*4+2][2*jA1] = a1.z; As[st][qA*4+2][2*jA1+1] = a1.z;
        As[st][qA*4+3][2*jA1] = a1.w; As[st][qA*4+3][2*jA1+1] = a1.w;
        Bs[st][qA*4+0][ml0] = b0v.x; Bs[st][qA*4+1][ml0] = b0v.y;
        Bs[st][qA*4+2][ml0] = b0v.z; Bs[st][qA*4+3][ml0] = b0v.w;
        Bs[st][qA*4+0][ml1] = b1v.x; Bs[st][qA*4+1][ml1] = b1v.y;
        Bs[st][qA*4+2][ml1] = b1v.z; Bs[st][qA*4+3][ml1] = b1v.w;
    }
    __syncthreads();

    int st = 0;
    for (int c = 0; c < 16; ++c) {
        if (c < 15) {
            const int k0 = (c + 1) * 16;
            a0  = *(const float4*)&W[(size_t)(jg0 + jA0) * 768 + 512 + k0 + qA * 4];
            a1  = *(const float4*)&W[(size_t)(jg0 + jA1) * 768 + 512 + k0 + qA * 4];
            b0v = *(const float4*)&emb[(size_t)id0 * NE + k0 + qA * 4];
            b1v = *(const float4*)&emb[(size_t)id1 * NE + k0 + qA * 4];
        }
#pragma unroll 4
        for (int kk = 0; kk < 16; ++kk) {
            ulonglong2 A01 = *(const ulonglong2*)&As[st][kk][ty * 16 + 0];
            ulonglong2 A23 = *(const ulonglong2*)&As[st][kk][ty * 16 + 4];
            ulonglong2 A45 = *(const ulonglong2*)&As[st][kk][ty * 16 + 8];
            ulonglong2 A67 = *(const ulonglong2*)&As[st][kk][ty * 16 + 12];
            u64 af[8] = {A01.x, A01.y, A23.x, A23.y, A45.x, A45.y, A67.x, A67.y};
            u64 bfr[4];
#pragma unroll
            for (int s = 0; s < 4; ++s)
                bfr[s] = *(const u64*)&Bs[st][kk][tx * 2 + s * 32];
#pragma unroll
            for (int jj = 0; jj < 8; ++jj)
#pragma unroll
                for (int s = 0; s < 4; ++s)
                    acc[jj][s] = fma2(bfr[s], af[jj], acc[jj][s]);
        }
        if (c < 15) {
            const int sn = st ^ 1;
            As[sn][qA*4+0][2*jA0] = a0.x; As[sn][qA*4+0][2*jA0+1] = a0.x;
            As[sn][qA*4+1][2*jA0] = a0.y; As[sn][qA*4+1][2*jA0+1] = a0.y;
            As[sn][qA*4+2][2*jA0] = a0.z; As[sn][qA*4+2][2*jA0+1] = a0.z;
            As[sn][qA*4+3][2*jA0] = a0.w; As[sn][qA*4+3][2*jA0+1] = a0.w;
            As[sn][qA*4+0][2*jA1] = a1.x; As[sn][qA*4+0][2*jA1+1] = a1.x;
            As[sn][qA*4+1][2*jA1] = a1.y; As[sn][qA*4+1][2*jA1+1] = a1.y;
            As[sn][qA*4+2][2*jA1] = a1.z; As[sn][qA*4+2][2*jA1+1] = a1.z;
            As[sn][qA*4+3][2*jA1] = a1.w; As[sn][qA*4+3][2*jA1+1] = a1.w;
            Bs[sn][qA*4+0][ml0] = b0v.x; Bs[sn][qA*4+1][ml0] = b0v.y;
            Bs[sn][qA*4+2][ml0] = b0v.z; Bs[sn][qA*4+3][ml0] = b0v.w;
            Bs[sn][qA*4+0][ml1] = b1v.x; Bs[sn][qA*4+1][ml1] = b1v.y;
            Bs[sn][qA*4+2][ml1] = b1v.z; Bs[sn][qA*4+3][ml1] = b1v.w;
        }
        __syncthreads();
        st ^= 1;
    }

#pragma unroll
    for (int jj = 0; jj < 8; ++jj) {
        const int row = gx * 128 + ty * 8 + jj;
        const float bv = bias[(gx & 3) * 128 + ty * 8 + jj];
#pragma unroll
        for (int s = 0; s < 4; ++s) {
            float2 v = upk2(acc[jj][s]);
            v.x += bv; v.y += bv;
            const int m = m0 + tx * 2 + s * 32;
            const size_t off = ((size_t)(m >> 6) * NG + row) * NB + (m & 63);
            *(float2*)&g_pre[off] = v;
        }
    }
}

// =====================================================================
// Phase 2: persistent recurrence.  128 CTAs x 256 threads.
// CTA(bid): rg = bid>>2 owns hidden rows 16rg..16rg+15 (all 4 gates);
//           bg = bid&3 owns batches 16bg..16bg+15.
// Thread: s = warpid (k-slice of 64), jl = (t&31)>>1, bgrp = t&1.
// Per-step sync: flag array (publish step+2 after threadfence).
// =====================================================================
__global__ void __launch_bounds__(256) lstm_recur(
    const float* __restrict__ Wf, const float* __restrict__ Wi,
    const float* __restrict__ Wo, const float* __restrict__ Wc)
{
    extern __shared__ float smem[];
    float* hs   = smem;                    // [k][16b]        8192 f (32 KB)
    float* pres = smem + 8192;             // [64row][16b]    1024 f (4 KB)
    u64*   red  = (u64*)(smem + 9216);     // [s][g][jl][9]   4608 u64 (36 KB)
    float* Wsm  = smem + 18432;            // [64row][514]    32896 f (128.5 KB)

    const int t    = threadIdx.x;
    const int bid  = blockIdx.x;
    const int rg   = bid >> 2;
    const int bg   = bid & 3;
    const int s    = t >> 5;
    const int w5   = t & 31;
    const int jl   = w5 >> 1;
    const int bgrp = w5 & 1;

    // ---- load W h-part into smem: Wsm[(g*16+j)*514 + k] ----
#pragma unroll
    for (int i = 0; i < 32; ++i) {
        const int slot = t + 256 * i;        // float4 slots 0..8191
        const int row  = slot >> 7;          // 0..63
        const int kq   = (slot & 127) * 4;
        const int g    = row >> 4, j2 = row & 15;
        const float* Wg = (g == 0) ? Wf : (g == 1) ? Wi : (g == 2) ? Wo : Wc;
        float4 v = *(const float4*)&Wg[(size_t)(rg * 16 + j2) * 768 + kq];
        float* d = Wsm + row * 514 + kq;
        d[0] = v.x; d[1] = v.y; d[2] = v.z; d[3] = v.w;
    }

    // ---- zero own slice of h[0], publish flag = 1 ----
    if (t < 128) {
        const int jj = t >> 3, bp = t & 7;
        *(float2*)&g_h[0][(rg * 16 + jj) * 64 + bg * 16 + 2 * bp] = make_float2(0.f, 0.f);
    }
    __threadfence();
    __syncthreads();
    if (t == 0) ((volatile int*)g_flags)[bid] = 1;

    float cva = 0.f, cvb = 0.f;
    float hma = -1e30f, hmb = -1e30f;

    for (int step = 0; step < T_SEQ; ++step) {
        // wait: all CTAs have published h for this step (and finished
        // reading the buffer we are about to overwrite)
        if (t < RECUR_CTAS) {
            while (((volatile int*)g_flags)[t] < step + 1) { }
        }
        __syncthreads();

        // load h tile (32 KB) + pre slice (4 KB) via L2 path
        {
            const float* hin = g_h[step & 1];
#pragma unroll
            for (int q = 0; q < 8; ++q) {
                const int idx = q * 256 + t;   // 16B chunk id
                cpa16(hs + idx * 4, hin + (idx >> 2) * 64 + bg * 16 + (idx & 3) * 4);
            }
            const int row = t >> 2, cc = t & 3;
            const int g = row >> 4, j2 = row & 15;
            cpa16(pres + row * 16 + cc * 4,
                  g_pre + ((size_t)step * NG + g * 512 + rg * 16 + j2) * 64 + bg * 16 + cc * 4);
            asm volatile("cp.async.commit_group;" ::: "memory");
            asm volatile("cp.async.wait_group 0;" ::: "memory");
        }
        __syncthreads();

        // ---- compute: 4 gates x 4 b-pairs over k-slice of 64 ----
        u64 acc[4][4];
#pragma unroll
        for (int g = 0; g < 4; ++g)
#pragma unroll
            for (int p = 0; p < 4; ++p) acc[g][p] = 0ull;

        const int k0 = s * 64;
#pragma unroll 4
        for (int kk = 0; kk < 64; ++kk) {
            const int k = k0 + kk;
            const float* hrow = hs + k * 16 + bgrp * 8;
            u64 h0 = *(const u64*)(hrow + 0);
            u64 h1 = *(const u64*)(hrow + 2);
            u64 h2 = *(const u64*)(hrow + 4);
            u64 h3 = *(const u64*)(hrow + 6);
#pragma unroll
            for (int g = 0; g < 4; ++g) {
                const u64 w2 = pkdup(Wsm[(g * 16 + jl) * 514 + k]);
                acc[g][0] = fma2(h0, w2, acc[g][0]);
                acc[g][1] = fma2(h1, w2, acc[g][1]);
                acc[g][2] = fma2(h2, w2, acc[g][2]);
                acc[g][3] = fma2(h3, w2, acc[g][3]);
            }
        }

        // ---- store k-partials ----
#pragma unroll
        for (int g = 0; g < 4; ++g)
#pragma unroll
            for (int p = 0; p < 4; ++p)
                red[((s * 4 + g) * 16 + jl) * 9 + bgrp * 4 + p] = acc[g][p];
        __syncthreads();

        // ---- combine + pointwise cell (threads 0..127 own (jj, bp)) ----
        if (t < 128) {
            const int jj = t >> 3, bp = t & 7;
            float2 gs[4];
#pragma unroll
            for (int g = 0; g < 4; ++g) {
                u64 sum = red[(g * 16 + jj) * 9 + bp];
#pragma unroll
                for (int ss = 1; ss < 8; ++ss)
                    sum = add2(sum, red[((ss * 4 + g) * 16 + jj) * 9 + bp]);
                float2 v  = upk2(sum);
                float2 pv = *(const float2*)&pres[(g * 16 + jj) * 16 + 2 * bp];
                gs[g] = make_float2(v.x + pv.x, v.y + pv.y);
            }
            const float fa = sigf(gs[0].x), fb = sigf(gs[0].y);
            const float ia = sigf(gs[1].x), ib = sigf(gs[1].y);
            const float oa = sigf(gs[2].x), ob = sigf(gs[2].y);
            const float ga = tanh_fast(gs[3].x), gb = tanh_fast(gs[3].y);
            cva = fa * cva + ia * ga;
            cvb = fb * cvb + ib * gb;
            const float ha = oa * tanh_fast(cva);
            const float hb = ob * tanh_fast(cvb);
            hma = fmaxf(hma, ha);
            hmb = fmaxf(hmb, hb);
            *(float2*)&g_h[(step + 1) & 1][(rg * 16 + jj) * 64 + bg * 16 + 2 * bp] =
                make_float2(ha, hb);
        }
        __threadfence();
        __syncthreads();
        if (t == 0) ((volatile int*)g_flags)[bid] = step + 2;
    }

    // ---- epilogue: write hmax ----
    if (t < 128) {
        const int jj = t >> 3, bp = t & 7;
        *(float2*)&g_hmax[(rg * 16 + jj) * 64 + bg * 16 + 2 * bp] = make_float2(hma, hmb);
    }

    // two centralized sense barriers (even count -> g_sense restored),
    // with flag reset in between: no CTA can still be polling when reset lands.
    int sense = 0;
#pragma unroll
    for (int rep = 0; rep < 2; ++rep) {
        __threadfence();
        __syncthreads();
        if (t == 0) {
            sense ^= 1;
            if (atomicAdd(&g_count, 1) == RECUR_CTAS - 1) {
                *(volatile int*)&g_count = 0;
                __threadfence();
                *(volatile int*)&g_sense = sense;
            } else {
                while (*(volatile int*)&g_sense != sense) { }
            }
            __threadfence();
        }
        __syncthreads();
        if (rep == 0 && t == 0) g_flags[bid] = 0;
    }
}

// =====================================================================
// Phase 3: logits[b][c] = fc_b[c] + sum_j hmax[j][b] * fc_w[c][j]
// =====================================================================
__global__ void fc_kernel(const float* __restrict__ fcw,
                          const float* __restrict__ fcb,
                          float* __restrict__ out)
{
    const int t = threadIdx.x;
    const int b = t & 63, c = t >> 6;
    float acc = 0.f;
#pragma unroll 8
    for (int j = 0; j < NH; ++j)
        acc += g_hmax[j * 64 + b] * fcw[c * NH + j];
    out[b * 4 + c] = acc + fcb[c];
}

// =====================================================================
extern "C" void kernel_launch(void* const* d_in, const int* in_sizes, int n_in,
                              void* d_out, int out_size)
{
    (void)in_sizes; (void)n_in; (void)out_size;
    const int*   ids = (const int*)  d_in[0];
    const float* emb = (const float*)d_in[1];
    const float* Wf  = (const float*)d_in[2];
    const float* bf  = (const float*)d_in[3];
    const float* Wi  = (const float*)d_in[4];
    const float* bi  = (const float*)d_in[5];
    const float* Wo  = (const float*)d_in[6];
    const float* bo  = (const float*)d_in[7];
    const float* Wc  = (const float*)d_in[8];
    const float* bc  = (const float*)d_in[9];
    const float* fcw = (const float*)d_in[10];
    const float* fcb = (const float*)d_in[11];
    float* out = (float*)d_out;

    // hs 32768 + pres 4096 + red 36864 + Wsm 131584 = 205312 B
    const int recur_smem = 205312;
    cudaFuncSetAttribute(lstm_recur, cudaFuncAttributeMaxDynamicSharedMemorySize, recur_smem);

    pre_gemm<<<dim3(16, 256), 256>>>(ids, emb, Wf, bf, Wi, bi, Wo, bo, Wc, bc);
    lstm_recur<<<RECUR_CTAS, 256, recur_smem>>>(Wf, Wi, Wo, Wc);
    fc_kernel<<<1, 256>>>(fcw, fcb, out);
}

// round 11
// speedup vs baseline: 1.8886x; 1.8886x over previous
#include <cuda_runtime.h>
#include <cuda_bf16.h>

// ---------------------------------------------------------------------------
// DisableGateLSTM: B=64, T=512, E=256, H=512, C=4
// Phase 1: pre[t][row][b] = bias[row] + x_t @ W[:,512:768]^T   (268 MB scratch)
// Phase 2: persistent recurrence, 128 CTAs = 32 row-groups x 4 batch-columns.
//          Weights in REGISTERS (128 regs/thread), h tile via cp.async.cg,
//          per-column flag barrier polled by one warp.
// Phase 3: logits = (max_t h) @ fc_w^T + fc_b
// ---------------------------------------------------------------------------

#define T_SEQ 512
#define NB    64
#define NE    256
#define NH    512
#define NG    2048
#define RECUR_CTAS 128

typedef unsigned long long u64;

static __device__ float g_pre[(size_t)T_SEQ * NG * NB];   // [t][row][b]
static __device__ float g_h[2][NH * NB];                  // ping-pong h, [j][b]
static __device__ float g_hmax[NH * NB];                  // [j][b]
static __device__ int   g_flags[RECUR_CTAS];              // [bg][rg] progress flags
static __device__ int   g_count;                          // epilogue barrier
static __device__ int   g_sense;

// ---------------- f32x2 helpers ----------------
static __device__ __forceinline__ u64 fma2(u64 a, u64 b, u64 c) {
    u64 d;
    asm("fma.rn.f32x2 %0, %1, %2, %3;" : "=l"(d) : "l"(a), "l"(b), "l"(c));
    return d;
}
static __device__ __forceinline__ u64 add2(u64 a, u64 b) {
    u64 d;
    asm("add.rn.f32x2 %0, %1, %2;" : "=l"(d) : "l"(a), "l"(b));
    return d;
}
static __device__ __forceinline__ u64 pkdup(float a) {
    u64 r; asm("mov.b64 %0, {%1, %1};" : "=l"(r) : "f"(a)); return r;
}
static __device__ __forceinline__ float2 upk2(u64 a) {
    float2 f;
    asm("mov.b64 {%0, %1}, %2;" : "=f"(f.x), "=f"(f.y) : "l"(a));
    return f;
}
static __device__ __forceinline__ float sigf(float x) {
    return 1.f / (1.f + __expf(-x));
}
static __device__ __forceinline__ float tanh_fast(float x) {
    return 2.f / (1.f + __expf(-2.f * x)) - 1.f;
}
// cp.async.cg: L2-only path => coherent with other SMs' global stores
static __device__ __forceinline__ void cpa16(void* dst, const void* src) {
    unsigned s = (unsigned)__cvta_generic_to_shared(dst);
    asm volatile("cp.async.cg.shared.global [%0], [%1], 16;" :: "r"(s), "l"(src) : "memory");
}

// =====================================================================
// Phase 1: pre-GEMM (unchanged: ~832us, fma 52%)
// =====================================================================
__global__ void __launch_bounds__(256, 2) pre_gemm(
    const int* __restrict__ ids, const float* __restrict__ emb,
    const float* __restrict__ Wf, const float* __restrict__ bf,
    const float* __restrict__ Wi, const float* __restrict__ bi,
    const float* __restrict__ Wo, const float* __restrict__ bo,
    const float* __restrict__ Wc, const float* __restrict__ bc)
{
    __shared__ float As[2][16][256];   // [kk][2*j] duplicated pairs
    __shared__ float Bs[2][16][128];   // [kk][m]

    const int t  = threadIdx.x;
    const int gx = blockIdx.x;
    const int m0 = blockIdx.y * 128;
    const int tx = t & 15, ty = t >> 4;

    const float* W    = (gx < 4) ? Wf : (gx < 8) ? Wi : (gx < 12) ? Wo : Wc;
    const float* bias = (gx < 4) ? bf : (gx < 8) ? bi : (gx < 12) ? bo : bc;
    const int jg0 = (gx & 3) * 128;

    const int jA0 = t >> 2;
    const int jA1 = jA0 + 64;
    const int qA  = t & 3;
    const int ml0 = t >> 2;
    const int ml1 = ml0 + 64;
    const int mg0 = m0 + ml0, mg1 = m0 + ml1;
    const int id0 = ids[(mg0 & 63) * T_SEQ + (mg0 >> 6)];
    const int id1 = ids[(mg1 & 63) * T_SEQ + (mg1 >> 6)];

    u64 acc[8][4];
#pragma unroll
    for (int jj = 0; jj < 8; ++jj)
#pragma unroll
        for (int s = 0; s < 4; ++s) acc[jj][s] = 0ull;

    float4 a0, a1, b0v, b1v;
    {
        const int k0 = 0;
        a0  = *(const float4*)&W[(size_t)(jg0 + jA0) * 768 + 512 + k0 + qA * 4];
        a1  = *(const float4*)&W[(size_t)(jg0 + jA1) * 768 + 512 + k0 + qA * 4];
        b0v = *(const float4*)&emb[(size_t)id0 * NE + k0 + qA * 4];
        b1v = *(const float4*)&emb[(size_t)id1 * NE + k0 + qA * 4];
    }
    {
        const int st = 0;
        As[st][qA*4+0][2*jA0] = a0.x; As[st][qA*4+0][2*jA0+1] = a0.x;
        As[st][qA*4+1][2*jA0] = a0.y; As[st][qA*4+1][2*jA0+1] = a0.y;
        As[st][qA*4+2][2*jA0] = a0.z; As[st][qA*4+2][2*jA0+1] = a0.z;
        As[st][qA*4+3][2*jA0] = a0.w; As[st][qA*4+3][2*jA0+1] = a0.w;
        As[st][qA*4+0][2*jA1] = a1.x; As[st][qA*4+0][2*jA1+1] = a1.x;
        As[st][qA*4+1][2*jA1] = a1.y; As[st][qA*4+1][2*jA1+1] = a1.y;
        As[st][qA*4+2][2*jA1] = a1.z; As[st][qA*4+2][2*jA1+1] = a1.z;
        As[st][qA*4+3][2*jA1] = a1.w; As[st][qA*4+3][2*jA1+1] = a1.w;
        Bs[st][qA*4+0][ml0] = b0v.x; Bs[st][qA*4+1][ml0] = b0v.y;
        Bs[st][qA*4+2][ml0] = b0v.z; Bs[st][qA*4+3][ml0] = b0v.w;
        Bs[st][qA*4+0][ml1] = b1v.x; Bs[st][qA*4+1][ml1] = b1v.y;
        Bs[st][qA*4+2][ml1] = b1v.z; Bs[st][qA*4+3][ml1] = b1v.w;
    }
    __syncthreads();

    int st = 0;
    for (int c = 0; c < 16; ++c) {
        if (c < 15) {
            const int k0 = (c + 1) * 16;
            a0  = *(const float4*)&W[(size_t)(jg0 + jA0) * 768 + 512 + k0 + qA * 4];
            a1  = *(const float4*)&W[(size_t)(jg0 + jA1) * 768 + 512 + k0 + qA * 4];
            b0v = *(const float4*)&emb[(size_t)id0 * NE + k0 + qA * 4];
            b1v = *(const float4*)&emb[(size_t)id1 * NE + k0 + qA * 4];
        }
#pragma unroll 4
        for (int kk = 0; kk < 16; ++kk) {
            ulonglong2 A01 = *(const ulonglong2*)&As[st][kk][ty * 16 + 0];
            ulonglong2 A23 = *(const ulonglong2*)&As[st][kk][ty * 16 + 4];
            ulonglong2 A45 = *(const ulonglong2*)&As[st][kk][ty * 16 + 8];
            ulonglong2 A67 = *(const ulonglong2*)&As[st][kk][ty * 16 + 12];
            u64 af[8] = {A01.x, A01.y, A23.x, A23.y, A45.x, A45.y, A67.x, A67.y};
            u64 bfr[4];
#pragma unroll
            for (int s = 0; s < 4; ++s)
                bfr[s] = *(const u64*)&Bs[st][kk][tx * 2 + s * 32];
#pragma unroll
            for (int jj = 0; jj < 8; ++jj)
#pragma unroll
                for (int s = 0; s < 4; ++s)
                    acc[jj][s] = fma2(bfr[s], af[jj], acc[jj][s]);
        }
        if (c < 15) {
            const int sn = st ^ 1;
            As[sn][qA*4+0][2*jA0] = a0.x; As[sn][qA*4+0][2*jA0+1] = a0.x;
            As[sn][qA*4+1][2*jA0] = a0.y; As[sn][qA*4+1][2*jA0+1] = a0.y;
            As[sn][qA*4+2][2*jA0] = a0.z; As[sn][qA*4+2][2*jA0+1] = a0.z;
            As[sn][qA*4+3][2*jA0] = a0.w; As[sn][qA*4+3][2*jA0+1] = a0.w;
            As[sn][qA*4+0][2*jA1] = a1.x; As[sn][qA*4+0][2*jA1+1] = a1.x;
            As[sn][qA*4+1][2*jA1] = a1.y; As[sn][qA*4+1][2*jA1+1] = a1.y;
            As[sn][qA*4+2][2*jA1] = a1.z; As[sn][qA*4+2][2*jA1+1] = a1.z;
            As[sn][qA*4+3][2*jA1] = a1.w; As[sn][qA*4+3][2*jA1+1] = a1.w;
            Bs[sn][qA*4+0][ml0] = b0v.x; Bs[sn][qA*4+1][ml0] = b0v.y;
            Bs[sn][qA*4+2][ml0] = b0v.z; Bs[sn][qA*4+3][ml0] = b0v.w;
            Bs[sn][qA*4+0][ml1] = b1v.x; Bs[sn][qA*4+1][ml1] = b1v.y;
            Bs[sn][qA*4+2][ml1] = b1v.z; Bs[sn][qA*4+3][ml1] = b1v.w;
        }
        __syncthreads();
        st ^= 1;
    }

#pragma unroll
    for (int jj = 0; jj < 8; ++jj) {
        const int row = gx * 128 + ty * 8 + jj;
        const float bv = bias[(gx & 3) * 128 + ty * 8 + jj];
#pragma unroll
        for (int s = 0; s < 4; ++s) {
            float2 v = upk2(acc[jj][s]);
            v.x += bv; v.y += bv;
            const int m = m0 + tx * 2 + s * 32;
            const size_t off = ((size_t)(m >> 6) * NG + row) * NB + (m & 63);
            *(float2*)&g_pre[off] = v;
        }
    }
}

// =====================================================================
// Phase 2: persistent recurrence.  128 CTAs x 256 threads.
// CTA(bid): rg = bid>>2 owns h-rows [16rg,16rg+16) (64 gate rows);
//           bg = bid&3 owns batches [16bg,16bg+16).
// Thread t: rw = t>>3 (2 gate rows), ks = t&7 (k-slice of 64).
// Weights: wreg[2][64] held in registers for the whole kernel.
// Sync: per-bg-column flags (32 CTAs), polled by warp 0 lanes.
// smem: hs[64kk][8ks][20f] 40KB | pres[64r][16b] 4KB | red[8ks][64r][9u64-pad]
// =====================================================================
__global__ void __launch_bounds__(256) lstm_recur(
    const float* __restrict__ Wf, const float* __restrict__ Wi,
    const float* __restrict__ Wo, const float* __restrict__ Wc)
{
    extern __shared__ float smem[];
    float* hs   = smem;                      // 64*8*20 = 10240 f (40960 B)
    float* pres = smem + 10240;              // 64*16   = 1024 f  (4096 B)
    u64*   red  = (u64*)(smem + 11264);      // 8*580   = 4640 u64 (37120 B)

    const int t   = threadIdx.x;
    const int bid = blockIdx.x;
    const int rg  = bid >> 2;
    const int bg  = bid & 3;
    const int rw  = t >> 3;                  // 0..31: gate-row pair
    const int ks  = t & 7;                   // k-slice of 64

    // ---- load weights into registers (once) ----
    float wreg[2][64];
    {
        const int r0 = rw * 2;
        const int g  = r0 >> 4;
        const int jl = r0 & 15;
        const float* Wg = (g == 0) ? Wf : (g == 1) ? Wi : (g == 2) ? Wo : Wc;
#pragma unroll
        for (int rr = 0; rr < 2; ++rr) {
            const float* p = &Wg[(size_t)(rg * 16 + jl + rr) * 768 + ks * 64];
#pragma unroll
            for (int q = 0; q < 16; ++q) {
                float4 v = *(const float4*)(p + q * 4);
                wreg[rr][q * 4 + 0] = v.x; wreg[rr][q * 4 + 1] = v.y;
                wreg[rr][q * 4 + 2] = v.z; wreg[rr][q * 4 + 3] = v.w;
            }
        }
    }

    // ---- zero own slice of h[0], publish flag = 1 ----
    if (t < 128) {
        const int jj = t >> 3, bp = t & 7;
        *(float2*)&g_h[0][(rg * 16 + jj) * 64 + bg * 16 + 2 * bp] = make_float2(0.f, 0.f);
    }
    __threadfence();
    __syncthreads();
    if (t == 0) ((volatile int*)g_flags)[bg * 32 + rg] = 1;

    float cva = 0.f, cvb = 0.f;
    float hma = -1e30f, hmb = -1e30f;

    for (int step = 0; step < T_SEQ; ++step) {
        // ---- prefetch pre slice (no cross-CTA dependency) ----
        {
            const int row = t >> 2, cc = t & 3;
            const int g = row >> 4, j2 = row & 15;
            cpa16(pres + row * 16 + cc * 4,
                  g_pre + ((size_t)step * NG + g * 512 + rg * 16 + j2) * 64 + bg * 16 + cc * 4);
            asm volatile("cp.async.commit_group;" ::: "memory");
        }

        // ---- wait: own column's 32 CTAs have published step's h ----
        if (t < 32) {
            volatile int* fl = g_flags + bg * 32;
            while (fl[t] < step + 1) { }
        }
        __syncthreads();

        // ---- load h column tile (32 KB) ----
        {
            const float* hin = g_h[step & 1];
#pragma unroll
            for (int i = 0; i < 8; ++i) {
                const int c  = i * 256 + t;          // 16B chunk id, 0..2047
                const int k  = c >> 2, q = c & 3;
                const int kk = k & 63, kss = k >> 6;
                cpa16(hs + (kk * 8 + kss) * 20 + q * 4,
                      hin + k * 64 + bg * 16 + q * 4);
            }
            asm volatile("cp.async.commit_group;" ::: "memory");
            asm volatile("cp.async.wait_group 0;" ::: "memory");
        }
        __syncthreads();

        // ---- compute: 2 rows x 8 b-pairs over k-slice of 64 (w in regs) ----
        u64 acc[2][8];
#pragma unroll
        for (int rr = 0; rr < 2; ++rr)
#pragma unroll
            for (int p = 0; p < 8; ++p) acc[rr][p] = 0ull;

#pragma unroll
        for (int kk = 0; kk < 64; ++kk) {
            const float* hrow = hs + (kk * 8 + ks) * 20;
            ulonglong2 ha = *(const ulonglong2*)(hrow + 0);   // pairs 0,1
            ulonglong2 hb = *(const ulonglong2*)(hrow + 4);   // pairs 2,3
            ulonglong2 hc = *(const ulonglong2*)(hrow + 8);   // pairs 4,5
            ulonglong2 hd = *(const ulonglong2*)(hrow + 12);  // pairs 6,7
            const u64 w0 = pkdup(wreg[0][kk]);
            const u64 w1 = pkdup(wreg[1][kk]);
            acc[0][0] = fma2(ha.x, w0, acc[0][0]);
            acc[0][1] = fma2(ha.y, w0, acc[0][1]);
            acc[0][2] = fma2(hb.x, w0, acc[0][2]);
            acc[0][3] = fma2(hb.y, w0, acc[0][3]);
            acc[0][4] = fma2(hc.x, w0, acc[0][4]);
            acc[0][5] = fma2(hc.y, w0, acc[0][5]);
            acc[0][6] = fma2(hd.x, w0, acc[0][6]);
            acc[0][7] = fma2(hd.y, w0, acc[0][7]);
            acc[1][0] = fma2(ha.x, w1, acc[1][0]);
            acc[1][1] = fma2(ha.y, w1, acc[1][1]);
            acc[1][2] = fma2(hb.x, w1, acc[1][2]);
            acc[1][3] = fma2(hb.y, w1, acc[1][3]);
            acc[1][4] = fma2(hc.x, w1, acc[1][4]);
            acc[1][5] = fma2(hc.y, w1, acc[1][5]);
            acc[1][6] = fma2(hd.x, w1, acc[1][6]);
            acc[1][7] = fma2(hd.y, w1, acc[1][7]);
        }

        // ---- store k-partials: red[ks*580 + r*9 + p] ----
#pragma unroll
        for (int rr = 0; rr < 2; ++rr)
#pragma unroll
            for (int p = 0; p < 8; ++p)
                red[ks * 580 + (rw * 2 + rr) * 9 + p] = acc[rr][p];
        __syncthreads();

        // ---- combine + pointwise cell (threads 0..127: jj = h-row, bp = b-pair) ----
        if (t < 128) {
            const int jj = t >> 3, bp = t & 7;
            float2 gs[4];
#pragma unroll
            for (int g = 0; g < 4; ++g) {
                const int rbase = (g * 16 + jj) * 9 + bp;
                u64 s0 = add2(red[0 * 580 + rbase], red[1 * 580 + rbase]);
                u64 s1 = add2(red[2 * 580 + rbase], red[3 * 580 + rbase]);
                u64 s2 = add2(red[4 * 580 + rbase], red[5 * 580 + rbase]);
                u64 s3 = add2(red[6 * 580 + rbase], red[7 * 580 + rbase]);
                u64 sum = add2(add2(s0, s1), add2(s2, s3));
                float2 v  = upk2(sum);
                float2 pv = *(const float2*)&pres[(g * 16 + jj) * 16 + 2 * bp];
                gs[g] = make_float2(v.x + pv.x, v.y + pv.y);
            }
            const float fa = sigf(gs[0].x), fb = sigf(gs[0].y);
            const float ia = sigf(gs[1].x), ib = sigf(gs[1].y);
            const float oa = sigf(gs[2].x), ob = sigf(gs[2].y);
            const float ga = tanh_fast(gs[3].x), gb = tanh_fast(gs[3].y);
            cva = fa * cva + ia * ga;
            cvb = fb * cvb + ib * gb;
            const float ha = oa * tanh_fast(cva);
            const float hb = ob * tanh_fast(cvb);
            hma = fmaxf(hma, ha);
            hmb = fmaxf(hmb, hb);
            *(float2*)&g_h[(step + 1) & 1][(rg * 16 + jj) * 64 + bg * 16 + 2 * bp] =
                make_float2(ha, hb);
            __threadfence();
        }
        __syncthreads();
        if (t == 0) ((volatile int*)g_flags)[bg * 32 + rg] = step + 2;
    }

    // ---- epilogue: write hmax ----
    if (t < 128) {
        const int jj = t >> 3, bp = t & 7;
        *(float2*)&g_hmax[(rg * 16 + jj) * 64 + bg * 16 + 2 * bp] = make_float2(hma, hmb);
    }

    // two centralized sense barriers (even count -> g_sense restored),
    // flag reset in between: no CTA can still be polling when reset lands.
    int sense = 0;
#pragma unroll
    for (int rep = 0; rep < 2; ++rep) {
        __threadfence();
        __syncthreads();
        if (t == 0) {
            sense ^= 1;
            if (atomicAdd(&g_count, 1) == RECUR_CTAS - 1) {
                *(volatile int*)&g_count = 0;
                __threadfence();
                *(volatile int*)&g_sense = sense;
            } else {
                while (*(volatile int*)&g_sense != sense) { }
            }
            __threadfence();
        }
        __syncthreads();
        if (rep == 0 && t == 0) g_flags[bg * 32 + rg] = 0;
    }
}

// =====================================================================
// Phase 3: logits[b][c] = fc_b[c] + sum_j hmax[j][b] * fc_w[c][j]
// =====================================================================
__global__ void fc_kernel(const float* __restrict__ fcw,
                          const float* __restrict__ fcb,
                          float* __restrict__ out)
{
    const int t = threadIdx.x;
    const int b = t & 63, c = t >> 6;
    float acc = 0.f;
#pragma unroll 8
    for (int j = 0; j < NH; ++j)
        acc += g_hmax[j * 64 + b] * fcw[c * NH + j];
    out[b * 4 + c] = acc + fcb[c];
}

// =====================================================================
extern "C" void kernel_launch(void* const* d_in, const int* in_sizes, int n_in,
                              void* d_out, int out_size)
{
    (void)in_sizes; (void)n_in; (void)out_size;
    const int*   ids = (const int*)  d_in[0];
    const float* emb = (const float*)d_in[1];
    const float* Wf  = (const float*)d_in[2];
    const float* bf  = (const float*)d_in[3];
    const float* Wi  = (const float*)d_in[4];
    const float* bi  = (const float*)d_in[5];
    const float* Wo  = (const float*)d_in[6];
    const float* bo  = (const float*)d_in[7];
    const float* Wc  = (const float*)d_in[8];
    const float* bc  = (const float*)d_in[9];
    const float* fcw = (const float*)d_in[10];
    const float* fcb = (const float*)d_in[11];
    float* out = (float*)d_out;

    // hs 40960 + pres 4096 + red 37120 = 82176 B
    const int recur_smem = 82176;
    cudaFuncSetAttribute(lstm_recur, cudaFuncAttributeMaxDynamicSharedMemorySize, recur_smem);

    pre_gemm<<<dim3(16, 256), 256>>>(ids, emb, Wf, bf, Wi, bi, Wo, bo, Wc, bc);
    lstm_recur<<<RECUR_CTAS, 256, recur_smem>>>(Wf, Wi, Wo, Wc);
    fc_kernel<<<1, 256>>>(fcw, fcb, out);
}